// round 15
// baseline (speedup 1.0000x reference)
#include <cuda_runtime.h>
#include <cuda_fp16.h>
#include <math.h>

// Problem constants
#define BB 8
#define TT 1024
#define IN_DIM 16
#define DD 256
#define HH 8
#define DK 32
#define LL 4
#define NROW (BB*TT)
#define LN_EPS 1e-5f

// -------- scratch (device globals) --------
__device__ float  g_h[NROW*DD];           // fp32 residual stream
__device__ __half g_h16[NROW*DD];         // fp16 hidden (GEMM A input)
__device__ __half g_qkvh[NROW*3*DD];      // fp16 qkv
__device__ __half g_attnh[NROW*DD];       // fp16 attention out
__device__ __half g_wqkv16[LL*3*DD*DD];   // fp16 Wqkv TRANSPOSED [l][n][k]
__device__ __half g_wout16[LL*DD*DD];     // fp16 Wout TRANSPOSED [l][n][k]
__device__ int    g_mki[LL*BB*HH];        // per (l,b,h) max ||k||^2 (float bits)

#define ONESH2 0x3C003C00u                // half2(1.0, 1.0)

// -------- helpers --------
__device__ __forceinline__ void mma16h(float* d, const unsigned* a, unsigned b0, unsigned b1) {
    asm volatile(
        "mma.sync.aligned.m16n8k16.row.col.f32.f16.f16.f32 "
        "{%0,%1,%2,%3}, {%4,%5,%6,%7}, {%8,%9}, {%0,%1,%2,%3};\n"
        : "+f"(d[0]), "+f"(d[1]), "+f"(d[2]), "+f"(d[3])
        : "r"(a[0]), "r"(a[1]), "r"(a[2]), "r"(a[3]), "r"(b0), "r"(b1));
}
__device__ __forceinline__ unsigned pkh2(float lo, float hi) {
    __half2 h = __floats2half2_rn(lo, hi);
    return *reinterpret_cast<unsigned*>(&h);
}
__device__ __forceinline__ unsigned ex2h2(unsigned x) {
    unsigned r;
    asm("ex2.approx.f16x2 %0, %1;" : "=r"(r) : "r"(x));
    return r;
}
// packed fp32x2 helpers (HMMA C-frag pairs are consecutive aligned regs)
__device__ __forceinline__ unsigned long long pk64(float lo, float hi) {
    unsigned long long r;
    asm("mov.b64 %0, {%1,%2};" : "=l"(r) : "f"(lo), "f"(hi));
    return r;
}
__device__ __forceinline__ unsigned long long fma2(unsigned long long a,
                                                   unsigned long long b,
                                                   unsigned long long c) {
    unsigned long long r;
    asm("fma.rn.f32x2 %0, %1, %2, %3;" : "=l"(r) : "l"(a), "l"(b), "l"(c));
    return r;
}
__device__ __forceinline__ unsigned f32x2h2(unsigned long long p) {
    float lo, hi; unsigned r;
    asm("mov.b64 {%0,%1}, %2;" : "=f"(lo), "=f"(hi) : "l"(p));
    asm("cvt.rn.f16x2.f32 %0, %1, %2;" : "=r"(r) : "f"(hi), "f"(lo));
    return r;
}
__device__ __forceinline__ unsigned prmt(unsigned a, unsigned b, unsigned sel) {
    unsigned r;
    asm("prmt.b32 %0, %1, %2, %3;" : "=r"(r) : "r"(a), "r"(b), "r"(sel));
    return r;
}
__device__ __forceinline__ void cp16(void* smem, const void* g) {
    unsigned a = (unsigned)__cvta_generic_to_shared(smem);
    asm volatile("cp.async.cg.shared.global [%0], [%1], 16;\n" :: "r"(a), "l"(g));
}
__device__ __forceinline__ void cp_commit() { asm volatile("cp.async.commit_group;\n"); }
template<int N> __device__ __forceinline__ void cp_wait() {
    asm volatile("cp.async.wait_group %0;\n" :: "n"(N));
}

// ============================================================
// 0. Weight transpose + fp16 convert, both tensors in one launch.
// ============================================================
__global__ void transp_kernel(const float* __restrict__ Wqkv,
                              const float* __restrict__ Wout,
                              __half* __restrict__ dq,
                              __half* __restrict__ dw) {
    __shared__ float tile[32][33];
    int k0 = blockIdx.x * 32;
    int by = blockIdx.y;
    int l  = blockIdx.z;
    const float* s; __half* d; int N, n0;
    if (by < 24) { N = 3 * DD; n0 = by * 32;
                   s = Wqkv + (size_t)l * DD * N; d = dq + (size_t)l * DD * N; }
    else         { N = DD;     n0 = (by - 24) * 32;
                   s = Wout + (size_t)l * DD * N; d = dw + (size_t)l * DD * N; }
    for (int i = threadIdx.y; i < 32; i += 8)
        tile[i][threadIdx.x] = s[(size_t)(k0 + i) * N + n0 + threadIdx.x];
    __syncthreads();
    for (int i = threadIdx.y; i < 32; i += 8)
        d[(size_t)(n0 + i) * DD + k0 + threadIdx.x] = __float2half_rn(tile[threadIdx.x][i]);
}

// ============================================================
// 1. Projection: h = x @ Wp + bp + pos  (fp32 + fp16 copy)
// ============================================================
__global__ void proj_kernel(const float* __restrict__ x,
                            const float* __restrict__ Wp,
                            const float* __restrict__ bp,
                            const float* __restrict__ pos) {
    int idx = blockIdx.x * blockDim.x + threadIdx.x;
    if (idx < LL * BB * HH) g_mki[idx] = 0;
    if (idx >= NROW * DD) return;
    int row = idx / DD;
    int col = idx - row * DD;
    int t = row & (TT - 1);
    const float* xr = x + row * IN_DIM;
    float s = bp[col] + pos[t * DD + col];
#pragma unroll
    for (int i = 0; i < IN_DIM; i++)
        s = fmaf(xr[i], Wp[i * DD + col], s);
    g_h[idx] = s;
    g_h16[idx] = __float2half_rn(s);
}

// ============================================================
// 2. QKV GEMM (fp16 m16n8k16): g_qkvh = g_h16 @ W^T + bqkv
//    RETILED: block 64x128, 8 warps of 32x32, 3 blocks/SM
//    (24 warps/SM for latency hiding; finer wave granularity).
//    4-stage cp.async ring. K-column blocks track max ||k||^2.
// ============================================================
#define QST_A 1280      // words per A stage (64*20)
#define QST_B 2560      // words per B stage (128*20)
#define QSMEM_BYTES ((4*(QST_A+QST_B))*4)   // 60KB

extern __shared__ float dynsmem[];

__global__ __launch_bounds__(256, 3)
void qkv_gemm_kernel(int layer, const float* __restrict__ bias) {
    unsigned* As = (unsigned*)dynsmem;          // [4][64][20]
    unsigned* Bs = As + 4 * QST_A;              // [4][128][20]
    const __half* __restrict__ A = g_h16;
    const __half* __restrict__ Bmat = g_wqkv16 + (size_t)layer * 3 * DD * DD; // [n][k]
    const int N = 3 * DD;

    const int tid  = threadIdx.x;
    const int lane = tid & 31;
    const int g    = lane >> 2;
    const int q    = lane & 3;
    const int warp = tid >> 5;
    const int wm   = (warp & 1) * 32;
    const int wn   = (warp >> 1) * 32;
    const int bm   = blockIdx.y * 64;
    const int bn   = blockIdx.x * 128;

    auto issue = [&](int s) {
        int k0 = s * 32;
        unsigned* Asb = As + (s & 3) * QST_A;
        unsigned* Bsb = Bs + (s & 3) * QST_B;
        {   // A: 64 rows x 4 chunks = 256 -> 1/thread
            int r = tid >> 2, cw = (tid & 3) * 4;
            cp16(&Asb[r * 20 + cw], A + (size_t)(bm + r) * DD + k0 + cw * 2);
        }
#pragma unroll
        for (int p = 0; p < 2; p++) {   // B: 128 rows x 4 chunks = 512 -> 2/thread
            int c = tid + p * 256;
            int r = c >> 2, cw = (c & 3) * 4;
            cp16(&Bsb[r * 20 + cw], Bmat + (size_t)(bn + r) * DD + k0 + cw * 2);
        }
    };

    float acc[2][4][4];
#pragma unroll
    for (int mc = 0; mc < 2; mc++)
#pragma unroll
        for (int nc = 0; nc < 4; nc++)
#pragma unroll
            for (int i = 0; i < 4; i++) acc[mc][nc][i] = 0.0f;

    issue(0); cp_commit();
    issue(1); cp_commit();
    issue(2); cp_commit();

    const int NS = DD / 32;   // 8
    for (int s = 0; s < NS; s++) {
        cp_wait<2>();
        __syncthreads();
        if (s + 3 < NS) issue(s + 3);
        cp_commit();

        const unsigned* Asb = As + (s & 3) * QST_A;
        const unsigned* Bsb = Bs + (s & 3) * QST_B;
#pragma unroll
        for (int kc = 0; kc < 2; kc++) {
            int kb = kc * 8;
            unsigned af[2][4], bf[4][2];
#pragma unroll
            for (int mc = 0; mc < 2; mc++) {
                int r = wm + mc * 16 + g;
                af[mc][0] = Asb[r * 20 + kb + q];
                af[mc][1] = Asb[(r + 8) * 20 + kb + q];
                af[mc][2] = Asb[r * 20 + kb + q + 4];
                af[mc][3] = Asb[(r + 8) * 20 + kb + q + 4];
            }
#pragma unroll
            for (int nc = 0; nc < 4; nc++) {
                int cc = wn + nc * 8 + g;
                bf[nc][0] = Bsb[cc * 20 + kb + q];
                bf[nc][1] = Bsb[cc * 20 + kb + q + 4];
            }
#pragma unroll
            for (int mc = 0; mc < 2; mc++)
#pragma unroll
                for (int nc = 0; nc < 4; nc++)
                    mma16h(acc[mc][nc], af[mc], bf[nc][0], bf[nc][1]);
        }
    }

    // epilogue: + bias, pack to fp16; K blocks also track max ||k||^2
    unsigned* qkw = reinterpret_cast<unsigned*>(g_qkvh);
    const bool isK = (bn == 256 || bn == 384);   // K cols [256,512)
    float mxss = 0.0f;
#pragma unroll
    for (int mc = 0; mc < 2; mc++) {
        float ssA = 0.0f, ssB = 0.0f;
#pragma unroll
        for (int nc = 0; nc < 4; nc++) {
            int row = bm + wm + mc * 16 + g;
            int col = bn + wn + nc * 8 + 2 * q;
            float2 bi = *(const float2*)&bias[col];
            float v0 = acc[mc][nc][0] + bi.x;
            float v1 = acc[mc][nc][1] + bi.y;
            float v2 = acc[mc][nc][2] + bi.x;
            float v3 = acc[mc][nc][3] + bi.y;
            qkw[(size_t)row * (N/2) + col/2]       = pkh2(v0, v1);
            qkw[(size_t)(row + 8) * (N/2) + col/2] = pkh2(v2, v3);
            ssA = fmaf(v0, v0, fmaf(v1, v1, ssA));
            ssB = fmaf(v2, v2, fmaf(v3, v3, ssB));
        }
        if (isK) {
            ssA += __shfl_xor_sync(0xffffffffu, ssA, 1);
            ssA += __shfl_xor_sync(0xffffffffu, ssA, 2);
            ssB += __shfl_xor_sync(0xffffffffu, ssB, 1);
            ssB += __shfl_xor_sync(0xffffffffu, ssB, 2);
            mxss = fmaxf(mxss, fmaxf(ssA, ssB));
        }
    }
    if (isK) {
        mxss = fmaxf(mxss, __shfl_xor_sync(0xffffffffu, mxss, 4));
        mxss = fmaxf(mxss, __shfl_xor_sync(0xffffffffu, mxss, 8));
        mxss = fmaxf(mxss, __shfl_xor_sync(0xffffffffu, mxss, 16));
        if (lane == 0) {
            int b = bm >> 10;                       // 1024 rows per batch
            int hd = (bn + wn - 256) >> 5;          // head of this warp
            atomicMax(&g_mki[layer * BB * HH + b * HH + hd], __float_as_int(mxss));
        }
    }
}

// ============================================================
// 3. Flash attention (unchanged from round 14, proven 41.7us):
//    fp16 MMA, Cauchy-Schwarz bounded softmax, ex2.approx.f16x2,
//    packed fma.rn.f32x2 exp args, l via ones-immediate MMA.
// ============================================================
__global__ __launch_bounds__(128, 4)
void attn_tc_kernel(int layer) {
    __shared__ unsigned Khs[2][32][20];   // [key][dim half2-word]
    __shared__ unsigned Vhs[2][16][40];   // [keypair][dim], stride 40

    const int tid  = threadIdx.x;
    const int lane = tid & 31;
    const int g    = lane >> 2;
    const int q    = lane & 3;
    const int warp = tid >> 5;
    const int h    = blockIdx.y;
    const int b    = blockIdx.z;
    const int qrow0 = blockIdx.x * 128 + warp * 32;

    const float qs = 0.17677669529663687f * 1.4426950408889634f; // scale*log2e
    const int RW = 3 * DD;
    const int RWW = RW / 2;

    const __half* kg = g_qkvh + (size_t)b * TT * RW + DD + h * DK;
    const __half* vg = g_qkvh + (size_t)b * TT * RW + 2 * DD + h * DK;
    const unsigned* qw = reinterpret_cast<const unsigned*>(
        g_qkvh + (size_t)(b * TT + qrow0) * RW + h * DK);

    const int kkey = tid >> 2;            // 0..31
    const int kwg  = (tid & 3) * 4;       // word offset 0,4,8,12
    const int vj  = tid >> 3;             // 0..15
    const int vdg = (tid & 7) * 4;        // dims vdg..vdg+3

    // prologue tile 0
    cp16(&Khs[0][kkey][kwg], kg + (size_t)kkey * RW + kwg * 2);
    cp_commit();
    {
        uint2 wa = *(const uint2*)(vg + (size_t)(2 * vj) * RW + vdg);
        uint2 wb = *(const uint2*)(vg + (size_t)(2 * vj + 1) * RW + vdg);
        uint4 p;
        p.x = prmt(wa.x, wb.x, 0x5410); p.y = prmt(wa.x, wb.x, 0x7632);
        p.z = prmt(wa.y, wb.y, 0x5410); p.w = prmt(wa.y, wb.y, 0x7632);
        *(uint4*)&Vhs[0][vj][vdg] = p;
    }

    // Q A-fragments (fp16 words straight from memory)
    unsigned qa[2][2][4];
#pragma unroll
    for (int mc = 0; mc < 2; mc++)
#pragma unroll
        for (int kc = 0; kc < 2; kc++) {
            int r = mc * 16 + g;
            qa[mc][kc][0] = qw[(size_t)r * RWW + kc * 8 + q];
            qa[mc][kc][1] = qw[(size_t)(r + 8) * RWW + kc * 8 + q];
            qa[mc][kc][2] = qw[(size_t)r * RWW + kc * 8 + q + 4];
            qa[mc][kc][3] = qw[(size_t)(r + 8) * RWW + kc * 8 + q + 4];
        }

    // Per-row exp bias: eb = 11 - ||q||*M_k*qs (packed f32x2 duplicates)
    const float Mk = sqrtf(__int_as_float(g_mki[layer * BB * HH + b * HH + h]));
    const unsigned long long qs2 = pk64(qs, qs);
    unsigned long long eb2[2][2];
#pragma unroll
    for (int mc = 0; mc < 2; mc++) {
        float a0 = 0.0f, a1 = 0.0f;
#pragma unroll
        for (int kc = 0; kc < 2; kc++) {
            float2 f;
            f = __half22float2(*reinterpret_cast<__half2*>(&qa[mc][kc][0]));
            a0 = fmaf(f.x, f.x, fmaf(f.y, f.y, a0));
            f = __half22float2(*reinterpret_cast<__half2*>(&qa[mc][kc][2]));
            a0 = fmaf(f.x, f.x, fmaf(f.y, f.y, a0));
            f = __half22float2(*reinterpret_cast<__half2*>(&qa[mc][kc][1]));
            a1 = fmaf(f.x, f.x, fmaf(f.y, f.y, a1));
            f = __half22float2(*reinterpret_cast<__half2*>(&qa[mc][kc][3]));
            a1 = fmaf(f.x, f.x, fmaf(f.y, f.y, a1));
        }
        a0 += __shfl_xor_sync(0xffffffffu, a0, 1);
        a0 += __shfl_xor_sync(0xffffffffu, a0, 2);
        a1 += __shfl_xor_sync(0xffffffffu, a1, 1);
        a1 += __shfl_xor_sync(0xffffffffu, a1, 2);
        float e0 = 11.0f - sqrtf(a0) * Mk * qs;
        float e1 = 11.0f - sqrtf(a1) * Mk * qs;
        eb2[mc][0] = pk64(e0, e0);
        eb2[mc][1] = pk64(e1, e1);
    }

    float oacc[2][4][4];
    float lacc[2][4];
#pragma unroll
    for (int mc = 0; mc < 2; mc++) {
#pragma unroll
        for (int i = 0; i < 4; i++) lacc[mc][i] = 0.0f;
#pragma unroll
        for (int nc = 0; nc < 4; nc++)
#pragma unroll
            for (int i = 0; i < 4; i++) oacc[mc][nc][i] = 0.0f;
    }

    const int NT = TT / 32;
    for (int t = 0; t < NT; t++) {
        int buf = t & 1;
        int nb  = buf ^ 1;
        uint2 wa, wb;
        if (t + 1 < NT) {
            int k0 = (t + 1) * 32;
            cp16(&Khs[nb][kkey][kwg], kg + (size_t)(k0 + kkey) * RW + kwg * 2);
            cp_commit();
            wa = *(const uint2*)(vg + (size_t)(k0 + 2 * vj) * RW + vdg);
            wb = *(const uint2*)(vg + (size_t)(k0 + 2 * vj + 1) * RW + vdg);
            cp_wait<1>();
        } else {
            cp_wait<0>();
        }
        __syncthreads();

        // ---- S = Q K^T (fp16 k16) ----
        float sf[2][4][4];
#pragma unroll
        for (int mc = 0; mc < 2; mc++)
#pragma unroll
            for (int nc = 0; nc < 4; nc++)
#pragma unroll
                for (int i = 0; i < 4; i++) sf[mc][nc][i] = 0.0f;

#pragma unroll
        for (int nc = 0; nc < 4; nc++) {
#pragma unroll
            for (int kc = 0; kc < 2; kc++) {
                unsigned b0 = Khs[buf][nc * 8 + g][kc * 8 + q];
                unsigned b1 = Khs[buf][nc * 8 + g][kc * 8 + q + 4];
                mma16h(sf[0][nc], qa[0][kc], b0, b1);
                mma16h(sf[1][nc], qa[1][kc], b0, b1);
            }
        }

        // ---- fused softmax + PV + l: exp args via packed f32x2 FMA ----
#pragma unroll
        for (int kk = 0; kk < 2; kk++) {
            unsigned pa0[4], pa1[4];
#pragma unroll
            for (int j = 0; j < 2; j++) {
                int nc = 2 * kk + j;
                pa0[2*j]   = ex2h2(f32x2h2(fma2(pk64(sf[0][nc][0], sf[0][nc][1]), qs2, eb2[0][0])));
                pa0[2*j+1] = ex2h2(f32x2h2(fma2(pk64(sf[0][nc][2], sf[0][nc][3]), qs2, eb2[0][1])));
                pa1[2*j]   = ex2h2(f32x2h2(fma2(pk64(sf[1][nc][0], sf[1][nc][1]), qs2, eb2[1][0])));
                pa1[2*j+1] = ex2h2(f32x2h2(fma2(pk64(sf[1][nc][2], sf[1][nc][3]), qs2, eb2[1][1])));
            }
#pragma unroll
            for (int dn = 0; dn < 4; dn++) {
                unsigned b0 = Vhs[buf][8*kk + q][dn * 8 + g];
                unsigned b1 = Vhs[buf][8*kk + q + 4][dn * 8 + g];
                mma16h(oacc[0][dn], pa0, b0, b1);
                mma16h(oacc[1][dn], pa1, b0, b1);
            }
            mma16h(lacc[0], pa0, ONESH2, ONESH2);
            mma16h(lacc[1], pa1, ONESH2, ONESH2);
        }

        // commit prefetched V tile
        if (t + 1 < NT) {
            uint4 p;
            p.x = prmt(wa.x, wb.x, 0x5410); p.y = prmt(wa.x, wb.x, 0x7632);
            p.z = prmt(wa.y, wb.y, 0x5410); p.w = prmt(wa.y, wb.y, 0x7632);
            *(uint4*)&Vhs[nb][vj][vdg] = p;
        }
        __syncthreads();
    }

    // ---- normalize (l from ones-MMA: no shuffles), store fp16 ----
    unsigned* ow = reinterpret_cast<unsigned*>(g_attnh);
#pragma unroll
    for (int mc = 0; mc < 2; mc++) {
        float inv0 = 1.0f / lacc[mc][0];
        float inv1 = 1.0f / lacc[mc][2];
        int r0 = b * TT + qrow0 + mc * 16 + g;
#pragma unroll
        for (int dn = 0; dn < 4; dn++) {
            int col = h * DK + dn * 8 + 2 * q;
            ow[(size_t)r0 * (DD/2) + col/2] =
                pkh2(oacc[mc][dn][0] * inv0, oacc[mc][dn][1] * inv0);
            ow[(size_t)(r0 + 8) * (DD/2) + col/2] =
                pkh2(oacc[mc][dn][2] * inv1, oacc[mc][dn][3] * inv1);
        }
    }
}

// ============================================================
// 4. Wout GEMM (fp16) + bias + residual + LayerNorm, fused.
//    Block 32x256 (full rows), 8 warps of 32x32, 256 blocks.
// ============================================================
#define WST_A 640       // words per A stage (32*20)
#define WST_B 5120      // words per B stage (256*20)
#define WRED_OFF (4*(WST_A+WST_B))
#define WSMEM_BYTES ((WRED_OFF+512)*4)

__global__ __launch_bounds__(256, 2)
void wout_ln_kernel(int layer, const float* __restrict__ bias,
                    const float* __restrict__ gamma,
                    const float* __restrict__ beta) {
    unsigned* As = (unsigned*)dynsmem;
    unsigned* Bs = As + 4 * WST_A;
    float* redS = dynsmem + WRED_OFF;       // [32][8]
    float* redQ = redS + 256;               // [32][8]
    const __half* __restrict__ A = g_attnh;
    const __half* __restrict__ Bmat = g_wout16 + (size_t)layer * DD * DD; // [n][k]

    const int tid  = threadIdx.x;
    const int lane = tid & 31;
    const int g    = lane >> 2;
    const int q    = lane & 3;
    const int warp = tid >> 5;
    const int wn   = warp * 32;
    const int bm   = blockIdx.x * 32;

    auto issue = [&](int s) {
        int k0 = s * 32;
        unsigned* Asb = As + (s & 3) * WST_A;
        unsigned* Bsb = Bs + (s & 3) * WST_B;
        if (tid < 128) {
            int r = tid >> 2, cw = (tid & 3) * 4;
            cp16(&Asb[r * 20 + cw], A + (size_t)(bm + r) * DD + k0 + cw * 2);
        }
#pragma unroll
        for (int p = 0; p < 4; p++) {
            int c = tid + p * 256;
            int r = c >> 2, cw = (c & 3) * 4;
            cp16(&Bsb[r * 20 + cw], Bmat + (size_t)r * DD + k0 + cw * 2);
        }
    };

    float acc[2][4][4];
#pragma unroll
    for (int mc = 0; mc < 2; mc++)
#pragma unroll
        for (int nc = 0; nc < 4; nc++)
#pragma unroll
            for (int i = 0; i < 4; i++) acc[mc][nc][i] = 0.0f;

    issue(0); cp_commit();
    issue(1); cp_commit();
    issue(2); cp_commit();

    const int NS = DD / 32;    // 8
    for (int s = 0; s < NS; s++) {
        cp_wait<2>();
        __syncthreads();
        if (s + 3 < NS) issue(s + 3);
        cp_commit();

        const unsigned* Asb = As + (s & 3) * WST_A;
        const unsigned* Bsb = Bs + (s & 3) * WST_B;
#pragma unroll
        for (int kc = 0; kc < 2; kc++) {
            int kb = kc * 8;
            unsigned af[2][4], bf[4][2];
#pragma unroll
            for (int mc = 0; mc < 2; mc++) {
                int r = mc * 16 + g;
                af[mc][0] = Asb[r * 20 + kb + q];
                af[mc][1] = Asb[(r + 8) * 20 + kb + q];
                af[mc][2] = Asb[r * 20 + kb + q + 4];
                af[mc][3] = Asb[(r + 8) * 20 + kb + q + 4];
            }
#pragma unroll
            for (int nc = 0; nc < 4; nc++) {
                int cc = wn + nc * 8 + g;
                bf[nc][0] = Bsb[cc * 20 + kb + q];
                bf[nc][1] = Bsb[cc * 20 + kb + q + 4];
            }
#pragma unroll
            for (int mc = 0; mc < 2; mc++)
#pragma unroll
                for (int nc = 0; nc < 4; nc++)
                    mma16h(acc[mc][nc], af[mc], bf[nc][0], bf[nc][1]);
        }
    }
    __syncthreads();

    // epilogue part 1: + bias + residual (fp32), partial row stats
#pragma unroll
    for (int mc = 0; mc < 2; mc++) {
        int rlo = bm + mc * 16 + g;
        float ssA = 0.f, sqA = 0.f, ssB = 0.f, sqB = 0.f;
#pragma unroll
        for (int nc = 0; nc < 4; nc++) {
            int col = wn + nc * 8 + 2 * q;
            float2 bi = *(const float2*)&bias[col];
            float2 h0 = *(const float2*)&g_h[(size_t)rlo * DD + col];
            float2 h1 = *(const float2*)&g_h[(size_t)(rlo + 8) * DD + col];
            acc[mc][nc][0] += bi.x + h0.x;
            acc[mc][nc][1] += bi.y + h0.y;
            acc[mc][nc][2] += bi.x + h1.x;
            acc[mc][nc][3] += bi.y + h1.y;
            ssA += acc[mc][nc][0] + acc[mc][nc][1];
            sqA += acc[mc][nc][0]*acc[mc][nc][0] + acc[mc][nc][1]*acc[mc][nc][1];
            ssB += acc[mc][nc][2] + acc[mc][nc][3];
            sqB += acc[mc][nc][2]*acc[mc][nc][2] + acc[mc][nc][3]*acc[mc][nc][3];
        }
        ssA += __shfl_xor_sync(0xffffffffu, ssA, 1); ssA += __shfl_xor_sync(0xffffffffu, ssA, 2);
        sqA += __shfl_xor_sync(0xffffffffu, sqA, 1); sqA += __shfl_xor_sync(0xffffffffu, sqA, 2);
        ssB += __shfl_xor_sync(0xffffffffu, ssB, 1); ssB += __shfl_xor_sync(0xffffffffu, ssB, 2);
        sqB += __shfl_xor_sync(0xffffffffu, sqB, 1); sqB += __shfl_xor_sync(0xffffffffu, sqB, 2);
        if (q == 0) {
            int rl = mc * 16 + g;
            redS[rl * 8 + warp] = ssA;  redQ[rl * 8 + warp] = sqA;
            redS[(rl + 8) * 8 + warp] = ssB;  redQ[(rl + 8) * 8 + warp] = sqB;
        }
    }
    __syncthreads();

    // epilogue part 2: normalize + store (fp32 + fp16)
    unsigned* hw = reinterpret_cast<unsigned*>(g_h16);
#pragma unroll
    for (int mc = 0; mc < 2; mc++) {
        int rlA = mc * 16 + g;
        int rlB = rlA + 8;
        float sA = 0.f, qA = 0.f, sB = 0.f, qB = 0.f;
#pragma unroll
        for (int w = 0; w < 8; w++) {
            sA += redS[rlA * 8 + w];  qA += redQ[rlA * 8 + w];
            sB += redS[rlB * 8 + w];  qB += redQ[rlB * 8 + w];
        }
        float muA = sA * (1.0f / DD);
        float muB = sB * (1.0f / DD);
        float rsA = rsqrtf(qA * (1.0f / DD) - muA * muA + LN_EPS);
        float rsB = rsqrtf(qB * (1.0f / DD) - muB * muB + LN_EPS);
        int rowA = bm + rlA;
#pragma unroll
        for (int nc = 0; nc < 4; nc++) {
            int col = wn + nc * 8 + 2 * q;
            float2 ga = *(const float2*)&gamma[col];
            float2 be = *(const float2*)&beta[col];
            float v0 = (acc[mc][nc][0] - muA) * rsA * ga.x + be.x;
            float v1 = (acc[mc][nc][1] - muA) * rsA * ga.y + be.y;
            float v2 = (acc[mc][nc][2] - muB) * rsB * ga.x + be.x;
            float v3 = (acc[mc][nc][3] - muB) * rsB * ga.y + be.y;
            *(float2*)&g_h[(size_t)rowA * DD + col]       = make_float2(v0, v1);
            *(float2*)&g_h[(size_t)(rowA + 8) * DD + col] = make_float2(v2, v3);
            hw[(size_t)rowA * (DD/2) + col/2]       = pkh2(v0, v1);
            hw[(size_t)(rowA + 8) * (DD/2) + col/2] = pkh2(v2, v3);
        }
    }
}

// ============================================================
// 5. Head
// ============================================================
__global__ void head_kernel(const float* __restrict__ Wo,
                            const float* __restrict__ bo,
                            float* __restrict__ out) {
    int b = blockIdx.x / 3;
    int j = blockIdx.x - b * 3;
    int lane = threadIdx.x;
    const float* hr = g_h + (size_t)(b * TT + (TT - 1)) * DD;
    float s = 0.0f;
    for (int d = lane; d < DD; d += 32)
        s = fmaf(hr[d], Wo[d * 3 + j], s);
#pragma unroll
    for (int o = 16; o > 0; o >>= 1)
        s += __shfl_xor_sync(0xffffffffu, s, o);
    if (lane == 0) out[b * 3 + j] = s + bo[j];
}

// ============================================================
// launch
// ============================================================
extern "C" void kernel_launch(void* const* d_in, const int* in_sizes, int n_in,
                              void* d_out, int out_size) {
    const float* x    = (const float*)d_in[0];
    const float* Wp   = (const float*)d_in[1];
    const float* bp   = (const float*)d_in[2];
    const float* pos  = (const float*)d_in[3];
    const float* Wqkv = (const float*)d_in[4];
    const float* bqkv = (const float*)d_in[5];
    const float* Wout = (const float*)d_in[6];
    const float* bout = (const float*)d_in[7];
    const float* ln_g = (const float*)d_in[8];
    const float* ln_b = (const float*)d_in[9];
    const float* Wo   = (const float*)d_in[10];
    const float* bo   = (const float*)d_in[11];
    float* out = (float*)d_out;

    cudaFuncSetAttribute(qkv_gemm_kernel, cudaFuncAttributeMaxDynamicSharedMemorySize, QSMEM_BYTES);
    cudaFuncSetAttribute(wout_ln_kernel,  cudaFuncAttributeMaxDynamicSharedMemorySize, WSMEM_BYTES);

    __half* d_wqkv16 = nullptr;
    __half* d_wout16 = nullptr;
    cudaGetSymbolAddress((void**)&d_wqkv16, g_wqkv16);
    cudaGetSymbolAddress((void**)&d_wout16, g_wout16);

    transp_kernel<<<dim3(DD/32, 32, LL), dim3(32, 8)>>>(Wqkv, Wout, d_wqkv16, d_wout16);
    proj_kernel<<<(NROW * DD + 255) / 256, 256>>>(x, Wp, bp, pos);

    for (int l = 0; l < LL; l++) {
        qkv_gemm_kernel<<<dim3((3 * DD) / 128, NROW / 64), 256, QSMEM_BYTES>>>(
            l, bqkv + (size_t)l * 3 * DD);
        attn_tc_kernel<<<dim3(TT / 128, HH, BB), 128>>>(l);
        wout_ln_kernel<<<NROW / 32, 256, WSMEM_BYTES>>>(
            l, bout + (size_t)l * DD, ln_g + (size_t)l * DD, ln_b + (size_t)l * DD);
    }

    head_kernel<<<24, 32>>>(Wo, bo, out);
}

// round 16
// speedup vs baseline: 1.0277x; 1.0277x over previous
#include <cuda_runtime.h>
#include <cuda_fp16.h>
#include <math.h>

// Problem constants
#define BB 8
#define TT 1024
#define IN_DIM 16
#define DD 256
#define HH 8
#define DK 32
#define LL 4
#define NROW (BB*TT)
#define LN_EPS 1e-5f

// -------- scratch (device globals) --------
__device__ float  g_h[NROW*DD];           // fp32 residual stream
__device__ __half g_h16[NROW*DD];         // fp16 hidden (GEMM A input)
__device__ __half g_qkvh[NROW*3*DD];      // fp16 qkv
__device__ __half g_attnh[NROW*DD];       // fp16 attention out
__device__ __half g_wqkv16[LL*3*DD*DD];   // fp16 Wqkv TRANSPOSED [l][n][k]
__device__ __half g_wout16[LL*DD*DD];     // fp16 Wout TRANSPOSED [l][n][k]
__device__ int    g_mki[LL*BB*HH];        // per (l,b,h) max ||k||^2 (float bits)

#define ONESH2 0x3C003C00u                // half2(1.0, 1.0)

// -------- helpers --------
__device__ __forceinline__ void mma16h(float* d, const unsigned* a, unsigned b0, unsigned b1) {
    asm volatile(
        "mma.sync.aligned.m16n8k16.row.col.f32.f16.f16.f32 "
        "{%0,%1,%2,%3}, {%4,%5,%6,%7}, {%8,%9}, {%0,%1,%2,%3};\n"
        : "+f"(d[0]), "+f"(d[1]), "+f"(d[2]), "+f"(d[3])
        : "r"(a[0]), "r"(a[1]), "r"(a[2]), "r"(a[3]), "r"(b0), "r"(b1));
}
__device__ __forceinline__ unsigned pkh2(float lo, float hi) {
    __half2 h = __floats2half2_rn(lo, hi);
    return *reinterpret_cast<unsigned*>(&h);
}
__device__ __forceinline__ unsigned ex2h2(unsigned x) {
    unsigned r;
    asm("ex2.approx.f16x2 %0, %1;" : "=r"(r) : "r"(x));
    return r;
}
// packed fp32x2 helpers (HMMA C-frag pairs are consecutive aligned regs)
__device__ __forceinline__ unsigned long long pk64(float lo, float hi) {
    unsigned long long r;
    asm("mov.b64 %0, {%1,%2};" : "=l"(r) : "f"(lo), "f"(hi));
    return r;
}
__device__ __forceinline__ unsigned long long fma2(unsigned long long a,
                                                   unsigned long long b,
                                                   unsigned long long c) {
    unsigned long long r;
    asm("fma.rn.f32x2 %0, %1, %2, %3;" : "=l"(r) : "l"(a), "l"(b), "l"(c));
    return r;
}
__device__ __forceinline__ unsigned f32x2h2(unsigned long long p) {
    float lo, hi; unsigned r;
    asm("mov.b64 {%0,%1}, %2;" : "=f"(lo), "=f"(hi) : "l"(p));
    asm("cvt.rn.f16x2.f32 %0, %1, %2;" : "=r"(r) : "f"(hi), "f"(lo));
    return r;
}
__device__ __forceinline__ unsigned prmt(unsigned a, unsigned b, unsigned sel) {
    unsigned r;
    asm("prmt.b32 %0, %1, %2, %3;" : "=r"(r) : "r"(a), "r"(b), "r"(sel));
    return r;
}
__device__ __forceinline__ void cp16(void* smem, const void* g) {
    unsigned a = (unsigned)__cvta_generic_to_shared(smem);
    asm volatile("cp.async.cg.shared.global [%0], [%1], 16;\n" :: "r"(a), "l"(g));
}
__device__ __forceinline__ void cp_commit() { asm volatile("cp.async.commit_group;\n"); }
template<int N> __device__ __forceinline__ void cp_wait() {
    asm volatile("cp.async.wait_group %0;\n" :: "n"(N));
}

// ============================================================
// 0. Weight transpose + fp16 convert, both tensors in one launch.
// ============================================================
__global__ void transp_kernel(const float* __restrict__ Wqkv,
                              const float* __restrict__ Wout,
                              __half* __restrict__ dq,
                              __half* __restrict__ dw) {
    __shared__ float tile[32][33];
    int k0 = blockIdx.x * 32;
    int by = blockIdx.y;
    int l  = blockIdx.z;
    const float* s; __half* d; int N, n0;
    if (by < 24) { N = 3 * DD; n0 = by * 32;
                   s = Wqkv + (size_t)l * DD * N; d = dq + (size_t)l * DD * N; }
    else         { N = DD;     n0 = (by - 24) * 32;
                   s = Wout + (size_t)l * DD * N; d = dw + (size_t)l * DD * N; }
    for (int i = threadIdx.y; i < 32; i += 8)
        tile[i][threadIdx.x] = s[(size_t)(k0 + i) * N + n0 + threadIdx.x];
    __syncthreads();
    for (int i = threadIdx.y; i < 32; i += 8)
        d[(size_t)(n0 + i) * DD + k0 + threadIdx.x] = __float2half_rn(tile[threadIdx.x][i]);
}

// ============================================================
// 1. Projection: h = x @ Wp + bp + pos  (fp32 + fp16 copy)
// ============================================================
__global__ void proj_kernel(const float* __restrict__ x,
                            const float* __restrict__ Wp,
                            const float* __restrict__ bp,
                            const float* __restrict__ pos) {
    int idx = blockIdx.x * blockDim.x + threadIdx.x;
    if (idx < LL * BB * HH) g_mki[idx] = 0;
    if (idx >= NROW * DD) return;
    int row = idx / DD;
    int col = idx - row * DD;
    int t = row & (TT - 1);
    const float* xr = x + row * IN_DIM;
    float s = bp[col] + pos[t * DD + col];
#pragma unroll
    for (int i = 0; i < IN_DIM; i++)
        s = fmaf(xr[i], Wp[i * DD + col], s);
    g_h[idx] = s;
    g_h16[idx] = __float2half_rn(s);
}

// ============================================================
// 2. QKV GEMM (fp16 m16n8k16): g_qkvh = g_h16 @ W^T + bqkv
//    Block 128x128, 8 warps (2m x 4n), warp 64x32, 2 blocks/SM.
//    4-stage cp.async ring. K-column blocks track max ||k||^2.
// ============================================================
#define QST_A 2560      // words per A stage (128*20)
#define QST_B 2560      // words per B stage (128*20)
#define QSMEM_BYTES ((4*(QST_A+QST_B))*4)

extern __shared__ float dynsmem[];

__global__ __launch_bounds__(256, 2)
void qkv_gemm_kernel(int layer, const float* __restrict__ bias) {
    unsigned* As = (unsigned*)dynsmem;          // [4][128][20]
    unsigned* Bs = As + 4 * QST_A;              // [4][128][20]
    const __half* __restrict__ A = g_h16;
    const __half* __restrict__ Bmat = g_wqkv16 + (size_t)layer * 3 * DD * DD; // [n][k]
    const int N = 3 * DD;

    const int tid  = threadIdx.x;
    const int lane = tid & 31;
    const int g    = lane >> 2;
    const int q    = lane & 3;
    const int warp = tid >> 5;
    const int wm   = (warp & 1) * 64;
    const int wn   = (warp >> 1) * 32;
    const int bm   = blockIdx.y * 128;
    const int bn   = blockIdx.x * 128;

    auto issue = [&](int s) {
        int k0 = s * 32;
        unsigned* Asb = As + (s & 3) * QST_A;
        unsigned* Bsb = Bs + (s & 3) * QST_B;
#pragma unroll
        for (int p = 0; p < 2; p++) {
            int c = tid + p * 256;
            int r = c >> 2, cw = (c & 3) * 4;
            cp16(&Asb[r * 20 + cw], A + (size_t)(bm + r) * DD + k0 + cw * 2);
        }
#pragma unroll
        for (int p = 0; p < 2; p++) {
            int c = tid + p * 256;
            int r = c >> 2, cw = (c & 3) * 4;
            cp16(&Bsb[r * 20 + cw], Bmat + (size_t)(bn + r) * DD + k0 + cw * 2);
        }
    };

    float acc[4][4][4];
#pragma unroll
    for (int mc = 0; mc < 4; mc++)
#pragma unroll
        for (int nc = 0; nc < 4; nc++)
#pragma unroll
            for (int i = 0; i < 4; i++) acc[mc][nc][i] = 0.0f;

    issue(0); cp_commit();
    issue(1); cp_commit();
    issue(2); cp_commit();

    const int NS = DD / 32;   // 8
    for (int s = 0; s < NS; s++) {
        cp_wait<2>();
        __syncthreads();
        if (s + 3 < NS) issue(s + 3);
        cp_commit();

        const unsigned* Asb = As + (s & 3) * QST_A;
        const unsigned* Bsb = Bs + (s & 3) * QST_B;
#pragma unroll
        for (int kc = 0; kc < 2; kc++) {
            int kb = kc * 8;
            unsigned af[4][4], bf[4][2];
#pragma unroll
            for (int mc = 0; mc < 4; mc++) {
                int r = wm + mc * 16 + g;
                af[mc][0] = Asb[r * 20 + kb + q];
                af[mc][1] = Asb[(r + 8) * 20 + kb + q];
                af[mc][2] = Asb[r * 20 + kb + q + 4];
                af[mc][3] = Asb[(r + 8) * 20 + kb + q + 4];
            }
#pragma unroll
            for (int nc = 0; nc < 4; nc++) {
                int cc = wn + nc * 8 + g;
                bf[nc][0] = Bsb[cc * 20 + kb + q];
                bf[nc][1] = Bsb[cc * 20 + kb + q + 4];
            }
#pragma unroll
            for (int mc = 0; mc < 4; mc++)
#pragma unroll
                for (int nc = 0; nc < 4; nc++)
                    mma16h(acc[mc][nc], af[mc], bf[nc][0], bf[nc][1]);
        }
    }

    // epilogue: + bias, pack to fp16; K blocks also track max ||k||^2
    unsigned* qkw = reinterpret_cast<unsigned*>(g_qkvh);
    const bool isK = (bn == 256 || bn == 384);   // K cols [256,512)
    float mxss = 0.0f;
#pragma unroll
    for (int mc = 0; mc < 4; mc++) {
        float ssA = 0.0f, ssB = 0.0f;
#pragma unroll
        for (int nc = 0; nc < 4; nc++) {
            int row = bm + wm + mc * 16 + g;
            int col = bn + wn + nc * 8 + 2 * q;
            float2 bi = *(const float2*)&bias[col];
            float v0 = acc[mc][nc][0] + bi.x;
            float v1 = acc[mc][nc][1] + bi.y;
            float v2 = acc[mc][nc][2] + bi.x;
            float v3 = acc[mc][nc][3] + bi.y;
            qkw[(size_t)row * (N/2) + col/2]       = pkh2(v0, v1);
            qkw[(size_t)(row + 8) * (N/2) + col/2] = pkh2(v2, v3);
            ssA = fmaf(v0, v0, fmaf(v1, v1, ssA));
            ssB = fmaf(v2, v2, fmaf(v3, v3, ssB));
        }
        if (isK) {
            ssA += __shfl_xor_sync(0xffffffffu, ssA, 1);
            ssA += __shfl_xor_sync(0xffffffffu, ssA, 2);
            ssB += __shfl_xor_sync(0xffffffffu, ssB, 1);
            ssB += __shfl_xor_sync(0xffffffffu, ssB, 2);
            mxss = fmaxf(mxss, fmaxf(ssA, ssB));
        }
    }
    if (isK) {
        mxss = fmaxf(mxss, __shfl_xor_sync(0xffffffffu, mxss, 4));
        mxss = fmaxf(mxss, __shfl_xor_sync(0xffffffffu, mxss, 8));
        mxss = fmaxf(mxss, __shfl_xor_sync(0xffffffffu, mxss, 16));
        if (lane == 0) {
            int b = bm >> 10;                       // 1024 rows per batch
            int hd = (bn + wn - 256) >> 5;          // head of this warp
            atomicMax(&g_mki[layer * BB * HH + b * HH + hd], __float_as_int(mxss));
        }
    }
}

// ============================================================
// 3. Flash attention: fp16 MMA, Cauchy-Schwarz bounded softmax,
//    ex2.approx.f16x2, packed fma.rn.f32x2 exp args,
//    l via ones-immediate MMA. 32-key double-buffered tiles.
// ============================================================
__global__ __launch_bounds__(128, 4)
void attn_tc_kernel(int layer) {
    __shared__ unsigned Khs[2][32][20];   // [key][dim half2-word]
    __shared__ unsigned Vhs[2][16][40];   // [keypair][dim], stride 40

    const int tid  = threadIdx.x;
    const int lane = tid & 31;
    const int g    = lane >> 2;
    const int q    = lane & 3;
    const int warp = tid >> 5;
    const int h    = blockIdx.y;
    const int b    = blockIdx.z;
    const int qrow0 = blockIdx.x * 128 + warp * 32;

    const float qs = 0.17677669529663687f * 1.4426950408889634f; // scale*log2e
    const int RW = 3 * DD;
    const int RWW = RW / 2;

    const __half* kg = g_qkvh + (size_t)b * TT * RW + DD + h * DK;
    const __half* vg = g_qkvh + (size_t)b * TT * RW + 2 * DD + h * DK;
    const unsigned* qw = reinterpret_cast<const unsigned*>(
        g_qkvh + (size_t)(b * TT + qrow0) * RW + h * DK);

    const int kkey = tid >> 2;            // 0..31
    const int kwg  = (tid & 3) * 4;       // word offset 0,4,8,12
    const int vj  = tid >> 3;             // 0..15
    const int vdg = (tid & 7) * 4;        // dims vdg..vdg+3

    // prologue tile 0
    cp16(&Khs[0][kkey][kwg], kg + (size_t)kkey * RW + kwg * 2);
    cp_commit();
    {
        uint2 wa = *(const uint2*)(vg + (size_t)(2 * vj) * RW + vdg);
        uint2 wb = *(const uint2*)(vg + (size_t)(2 * vj + 1) * RW + vdg);
        uint4 p;
        p.x = prmt(wa.x, wb.x, 0x5410); p.y = prmt(wa.x, wb.x, 0x7632);
        p.z = prmt(wa.y, wb.y, 0x5410); p.w = prmt(wa.y, wb.y, 0x7632);
        *(uint4*)&Vhs[0][vj][vdg] = p;
    }

    // Q A-fragments (fp16 words straight from memory)
    unsigned qa[2][2][4];
#pragma unroll
    for (int mc = 0; mc < 2; mc++)
#pragma unroll
        for (int kc = 0; kc < 2; kc++) {
            int r = mc * 16 + g;
            qa[mc][kc][0] = qw[(size_t)r * RWW + kc * 8 + q];
            qa[mc][kc][1] = qw[(size_t)(r + 8) * RWW + kc * 8 + q];
            qa[mc][kc][2] = qw[(size_t)r * RWW + kc * 8 + q + 4];
            qa[mc][kc][3] = qw[(size_t)(r + 8) * RWW + kc * 8 + q + 4];
        }

    // Per-row exp bias: eb = 11 - ||q||*M_k*qs (packed f32x2 duplicates)
    const float Mk = sqrtf(__int_as_float(g_mki[layer * BB * HH + b * HH + h]));
    const unsigned long long qs2 = pk64(qs, qs);
    unsigned long long eb2[2][2];
#pragma unroll
    for (int mc = 0; mc < 2; mc++) {
        float a0 = 0.0f, a1 = 0.0f;
#pragma unroll
        for (int kc = 0; kc < 2; kc++) {
            float2 f;
            f = __half22float2(*reinterpret_cast<__half2*>(&qa[mc][kc][0]));
            a0 = fmaf(f.x, f.x, fmaf(f.y, f.y, a0));
            f = __half22float2(*reinterpret_cast<__half2*>(&qa[mc][kc][2]));
            a0 = fmaf(f.x, f.x, fmaf(f.y, f.y, a0));
            f = __half22float2(*reinterpret_cast<__half2*>(&qa[mc][kc][1]));
            a1 = fmaf(f.x, f.x, fmaf(f.y, f.y, a1));
            f = __half22float2(*reinterpret_cast<__half2*>(&qa[mc][kc][3]));
            a1 = fmaf(f.x, f.x, fmaf(f.y, f.y, a1));
        }
        a0 += __shfl_xor_sync(0xffffffffu, a0, 1);
        a0 += __shfl_xor_sync(0xffffffffu, a0, 2);
        a1 += __shfl_xor_sync(0xffffffffu, a1, 1);
        a1 += __shfl_xor_sync(0xffffffffu, a1, 2);
        float e0 = 11.0f - sqrtf(a0) * Mk * qs;
        float e1 = 11.0f - sqrtf(a1) * Mk * qs;
        eb2[mc][0] = pk64(e0, e0);
        eb2[mc][1] = pk64(e1, e1);
    }

    float oacc[2][4][4];
    float lacc[2][4];
#pragma unroll
    for (int mc = 0; mc < 2; mc++) {
#pragma unroll
        for (int i = 0; i < 4; i++) lacc[mc][i] = 0.0f;
#pragma unroll
        for (int nc = 0; nc < 4; nc++)
#pragma unroll
            for (int i = 0; i < 4; i++) oacc[mc][nc][i] = 0.0f;
    }

    const int NT = TT / 32;
    for (int t = 0; t < NT; t++) {
        int buf = t & 1;
        int nb  = buf ^ 1;
        uint2 wa, wb;
        if (t + 1 < NT) {
            int k0 = (t + 1) * 32;
            cp16(&Khs[nb][kkey][kwg], kg + (size_t)(k0 + kkey) * RW + kwg * 2);
            cp_commit();
            wa = *(const uint2*)(vg + (size_t)(k0 + 2 * vj) * RW + vdg);
            wb = *(const uint2*)(vg + (size_t)(k0 + 2 * vj + 1) * RW + vdg);
            cp_wait<1>();
        } else {
            cp_wait<0>();
        }
        __syncthreads();

        // ---- S = Q K^T (fp16 k16) ----
        float sf[2][4][4];
#pragma unroll
        for (int mc = 0; mc < 2; mc++)
#pragma unroll
            for (int nc = 0; nc < 4; nc++)
#pragma unroll
                for (int i = 0; i < 4; i++) sf[mc][nc][i] = 0.0f;

#pragma unroll
        for (int nc = 0; nc < 4; nc++) {
#pragma unroll
            for (int kc = 0; kc < 2; kc++) {
                unsigned b0 = Khs[buf][nc * 8 + g][kc * 8 + q];
                unsigned b1 = Khs[buf][nc * 8 + g][kc * 8 + q + 4];
                mma16h(sf[0][nc], qa[0][kc], b0, b1);
                mma16h(sf[1][nc], qa[1][kc], b0, b1);
            }
        }

        // ---- fused softmax + PV + l: exp args via packed f32x2 FMA ----
#pragma unroll
        for (int kk = 0; kk < 2; kk++) {
            unsigned pa0[4], pa1[4];
#pragma unroll
            for (int j = 0; j < 2; j++) {
                int nc = 2 * kk + j;
                pa0[2*j]   = ex2h2(f32x2h2(fma2(pk64(sf[0][nc][0], sf[0][nc][1]), qs2, eb2[0][0])));
                pa0[2*j+1] = ex2h2(f32x2h2(fma2(pk64(sf[0][nc][2], sf[0][nc][3]), qs2, eb2[0][1])));
                pa1[2*j]   = ex2h2(f32x2h2(fma2(pk64(sf[1][nc][0], sf[1][nc][1]), qs2, eb2[1][0])));
                pa1[2*j+1] = ex2h2(f32x2h2(fma2(pk64(sf[1][nc][2], sf[1][nc][3]), qs2, eb2[1][1])));
            }
#pragma unroll
            for (int dn = 0; dn < 4; dn++) {
                unsigned b0 = Vhs[buf][8*kk + q][dn * 8 + g];
                unsigned b1 = Vhs[buf][8*kk + q + 4][dn * 8 + g];
                mma16h(oacc[0][dn], pa0, b0, b1);
                mma16h(oacc[1][dn], pa1, b0, b1);
            }
            mma16h(lacc[0], pa0, ONESH2, ONESH2);
            mma16h(lacc[1], pa1, ONESH2, ONESH2);
        }

        // commit prefetched V tile
        if (t + 1 < NT) {
            uint4 p;
            p.x = prmt(wa.x, wb.x, 0x5410); p.y = prmt(wa.x, wb.x, 0x7632);
            p.z = prmt(wa.y, wb.y, 0x5410); p.w = prmt(wa.y, wb.y, 0x7632);
            *(uint4*)&Vhs[nb][vj][vdg] = p;
        }
        __syncthreads();
    }

    // ---- normalize (l from ones-MMA: no shuffles), store fp16 ----
    unsigned* ow = reinterpret_cast<unsigned*>(g_attnh);
#pragma unroll
    for (int mc = 0; mc < 2; mc++) {
        float inv0 = 1.0f / lacc[mc][0];
        float inv1 = 1.0f / lacc[mc][2];
        int r0 = b * TT + qrow0 + mc * 16 + g;
#pragma unroll
        for (int dn = 0; dn < 4; dn++) {
            int col = h * DK + dn * 8 + 2 * q;
            ow[(size_t)r0 * (DD/2) + col/2] =
                pkh2(oacc[mc][dn][0] * inv0, oacc[mc][dn][1] * inv0);
            ow[(size_t)(r0 + 8) * (DD/2) + col/2] =
                pkh2(oacc[mc][dn][2] * inv1, oacc[mc][dn][3] * inv1);
        }
    }
}

// ============================================================
// 4. Wout GEMM (fp16) + bias + residual + LayerNorm, fused.
//    Block 32x256 (full rows), 8 warps of 32x32, 256 blocks.
// ============================================================
#define WST_A 640       // words per A stage (32*20)
#define WST_B 5120      // words per B stage (256*20)
#define WRED_OFF (4*(WST_A+WST_B))
#define WSMEM_BYTES ((WRED_OFF+512)*4)

__global__ __launch_bounds__(256, 2)
void wout_ln_kernel(int layer, const float* __restrict__ bias,
                    const float* __restrict__ gamma,
                    const float* __restrict__ beta) {
    unsigned* As = (unsigned*)dynsmem;
    unsigned* Bs = As + 4 * WST_A;
    float* redS = dynsmem + WRED_OFF;       // [32][8]
    float* redQ = redS + 256;               // [32][8]
    const __half* __restrict__ A = g_attnh;
    const __half* __restrict__ Bmat = g_wout16 + (size_t)layer * DD * DD; // [n][k]

    const int tid  = threadIdx.x;
    const int lane = tid & 31;
    const int g    = lane >> 2;
    const int q    = lane & 3;
    const int warp = tid >> 5;
    const int wn   = warp * 32;
    const int bm   = blockIdx.x * 32;

    auto issue = [&](int s) {
        int k0 = s * 32;
        unsigned* Asb = As + (s & 3) * WST_A;
        unsigned* Bsb = Bs + (s & 3) * WST_B;
        if (tid < 128) {
            int r = tid >> 2, cw = (tid & 3) * 4;
            cp16(&Asb[r * 20 + cw], A + (size_t)(bm + r) * DD + k0 + cw * 2);
        }
#pragma unroll
        for (int p = 0; p < 4; p++) {
            int c = tid + p * 256;
            int r = c >> 2, cw = (c & 3) * 4;
            cp16(&Bsb[r * 20 + cw], Bmat + (size_t)r * DD + k0 + cw * 2);
        }
    };

    float acc[2][4][4];
#pragma unroll
    for (int mc = 0; mc < 2; mc++)
#pragma unroll
        for (int nc = 0; nc < 4; nc++)
#pragma unroll
            for (int i = 0; i < 4; i++) acc[mc][nc][i] = 0.0f;

    issue(0); cp_commit();
    issue(1); cp_commit();
    issue(2); cp_commit();

    const int NS = DD / 32;    // 8
    for (int s = 0; s < NS; s++) {
        cp_wait<2>();
        __syncthreads();
        if (s + 3 < NS) issue(s + 3);
        cp_commit();

        const unsigned* Asb = As + (s & 3) * WST_A;
        const unsigned* Bsb = Bs + (s & 3) * WST_B;
#pragma unroll
        for (int kc = 0; kc < 2; kc++) {
            int kb = kc * 8;
            unsigned af[2][4], bf[4][2];
#pragma unroll
            for (int mc = 0; mc < 2; mc++) {
                int r = mc * 16 + g;
                af[mc][0] = Asb[r * 20 + kb + q];
                af[mc][1] = Asb[(r + 8) * 20 + kb + q];
                af[mc][2] = Asb[r * 20 + kb + q + 4];
                af[mc][3] = Asb[(r + 8) * 20 + kb + q + 4];
            }
#pragma unroll
            for (int nc = 0; nc < 4; nc++) {
                int cc = wn + nc * 8 + g;
                bf[nc][0] = Bsb[cc * 20 + kb + q];
                bf[nc][1] = Bsb[cc * 20 + kb + q + 4];
            }
#pragma unroll
            for (int mc = 0; mc < 2; mc++)
#pragma unroll
                for (int nc = 0; nc < 4; nc++)
                    mma16h(acc[mc][nc], af[mc], bf[nc][0], bf[nc][1]);
        }
    }
    __syncthreads();

    // epilogue part 1: + bias + residual (fp32), partial row stats
#pragma unroll
    for (int mc = 0; mc < 2; mc++) {
        int rlo = bm + mc * 16 + g;
        float ssA = 0.f, sqA = 0.f, ssB = 0.f, sqB = 0.f;
#pragma unroll
        for (int nc = 0; nc < 4; nc++) {
            int col = wn + nc * 8 + 2 * q;
            float2 bi = *(const float2*)&bias[col];
            float2 h0 = *(const float2*)&g_h[(size_t)rlo * DD + col];
            float2 h1 = *(const float2*)&g_h[(size_t)(rlo + 8) * DD + col];
            acc[mc][nc][0] += bi.x + h0.x;
            acc[mc][nc][1] += bi.y + h0.y;
            acc[mc][nc][2] += bi.x + h1.x;
            acc[mc][nc][3] += bi.y + h1.y;
            ssA += acc[mc][nc][0] + acc[mc][nc][1];
            sqA += acc[mc][nc][0]*acc[mc][nc][0] + acc[mc][nc][1]*acc[mc][nc][1];
            ssB += acc[mc][nc][2] + acc[mc][nc][3];
            sqB += acc[mc][nc][2]*acc[mc][nc][2] + acc[mc][nc][3]*acc[mc][nc][3];
        }
        ssA += __shfl_xor_sync(0xffffffffu, ssA, 1); ssA += __shfl_xor_sync(0xffffffffu, ssA, 2);
        sqA += __shfl_xor_sync(0xffffffffu, sqA, 1); sqA += __shfl_xor_sync(0xffffffffu, sqA, 2);
        ssB += __shfl_xor_sync(0xffffffffu, ssB, 1); ssB += __shfl_xor_sync(0xffffffffu, ssB, 2);
        sqB += __shfl_xor_sync(0xffffffffu, sqB, 1); sqB += __shfl_xor_sync(0xffffffffu, sqB, 2);
        if (q == 0) {
            int rl = mc * 16 + g;
            redS[rl * 8 + warp] = ssA;  redQ[rl * 8 + warp] = sqA;
            redS[(rl + 8) * 8 + warp] = ssB;  redQ[(rl + 8) * 8 + warp] = sqB;
        }
    }
    __syncthreads();

    // epilogue part 2: normalize + store (fp32 + fp16)
    unsigned* hw = reinterpret_cast<unsigned*>(g_h16);
#pragma unroll
    for (int mc = 0; mc < 2; mc++) {
        int rlA = mc * 16 + g;
        int rlB = rlA + 8;
        float sA = 0.f, qA = 0.f, sB = 0.f, qB = 0.f;
#pragma unroll
        for (int w = 0; w < 8; w++) {
            sA += redS[rlA * 8 + w];  qA += redQ[rlA * 8 + w];
            sB += redS[rlB * 8 + w];  qB += redQ[rlB * 8 + w];
        }
        float muA = sA * (1.0f / DD);
        float muB = sB * (1.0f / DD);
        float rsA = rsqrtf(qA * (1.0f / DD) - muA * muA + LN_EPS);
        float rsB = rsqrtf(qB * (1.0f / DD) - muB * muB + LN_EPS);
        int rowA = bm + rlA;
#pragma unroll
        for (int nc = 0; nc < 4; nc++) {
            int col = wn + nc * 8 + 2 * q;
            float2 ga = *(const float2*)&gamma[col];
            float2 be = *(const float2*)&beta[col];
            float v0 = (acc[mc][nc][0] - muA) * rsA * ga.x + be.x;
            float v1 = (acc[mc][nc][1] - muA) * rsA * ga.y + be.y;
            float v2 = (acc[mc][nc][2] - muB) * rsB * ga.x + be.x;
            float v3 = (acc[mc][nc][3] - muB) * rsB * ga.y + be.y;
            *(float2*)&g_h[(size_t)rowA * DD + col]       = make_float2(v0, v1);
            *(float2*)&g_h[(size_t)(rowA + 8) * DD + col] = make_float2(v2, v3);
            hw[(size_t)rowA * (DD/2) + col/2]       = pkh2(v0, v1);
            hw[(size_t)(rowA + 8) * (DD/2) + col/2] = pkh2(v2, v3);
        }
    }
}

// ============================================================
// 5. Head
// ============================================================
__global__ void head_kernel(const float* __restrict__ Wo,
                            const float* __restrict__ bo,
                            float* __restrict__ out) {
    int b = blockIdx.x / 3;
    int j = blockIdx.x - b * 3;
    int lane = threadIdx.x;
    const float* hr = g_h + (size_t)(b * TT + (TT - 1)) * DD;
    float s = 0.0f;
    for (int d = lane; d < DD; d += 32)
        s = fmaf(hr[d], Wo[d * 3 + j], s);
#pragma unroll
    for (int o = 16; o > 0; o >>= 1)
        s += __shfl_xor_sync(0xffffffffu, s, o);
    if (lane == 0) out[b * 3 + j] = s + bo[j];
}

// ============================================================
// launch
// ============================================================
extern "C" void kernel_launch(void* const* d_in, const int* in_sizes, int n_in,
                              void* d_out, int out_size) {
    const float* x    = (const float*)d_in[0];
    const float* Wp   = (const float*)d_in[1];
    const float* bp   = (const float*)d_in[2];
    const float* pos  = (const float*)d_in[3];
    const float* Wqkv = (const float*)d_in[4];
    const float* bqkv = (const float*)d_in[5];
    const float* Wout = (const float*)d_in[6];
    const float* bout = (const float*)d_in[7];
    const float* ln_g = (const float*)d_in[8];
    const float* ln_b = (const float*)d_in[9];
    const float* Wo   = (const float*)d_in[10];
    const float* bo   = (const float*)d_in[11];
    float* out = (float*)d_out;

    cudaFuncSetAttribute(qkv_gemm_kernel, cudaFuncAttributeMaxDynamicSharedMemorySize, QSMEM_BYTES);
    cudaFuncSetAttribute(wout_ln_kernel,  cudaFuncAttributeMaxDynamicSharedMemorySize, WSMEM_BYTES);

    __half* d_wqkv16 = nullptr;
    __half* d_wout16 = nullptr;
    cudaGetSymbolAddress((void**)&d_wqkv16, g_wqkv16);
    cudaGetSymbolAddress((void**)&d_wout16, g_wout16);

    transp_kernel<<<dim3(DD/32, 32, LL), dim3(32, 8)>>>(Wqkv, Wout, d_wqkv16, d_wout16);
    proj_kernel<<<(NROW * DD + 255) / 256, 256>>>(x, Wp, bp, pos);

    for (int l = 0; l < LL; l++) {
        qkv_gemm_kernel<<<dim3((3 * DD) / 128, NROW / 128), 256, QSMEM_BYTES>>>(
            l, bqkv + (size_t)l * 3 * DD);
        attn_tc_kernel<<<dim3(TT / 128, HH, BB), 128>>>(l);
        wout_ln_kernel<<<NROW / 32, 256, WSMEM_BYTES>>>(
            l, bout + (size_t)l * DD, ln_g + (size_t)l * DD, ln_b + (size_t)l * DD);
    }

    head_kernel<<<24, 32>>>(Wo, bo, out);
}

// round 17
// speedup vs baseline: 1.0899x; 1.0604x over previous
#include <cuda_runtime.h>
#include <cuda_fp16.h>
#include <math.h>

// Problem constants
#define BB 8
#define TT 1024
#define IN_DIM 16
#define DD 256
#define HH 8
#define DK 32
#define LL 4
#define NROW (BB*TT)
#define LN_EPS 1e-5f

// -------- scratch (device globals) --------
__device__ float  g_h[NROW*DD];           // fp32 residual stream
__device__ __half g_h16[NROW*DD];         // fp16 hidden (GEMM A input)
__device__ __half g_qkvh[NROW*3*DD];      // fp16 qkv
__device__ __half g_attnh[NROW*DD];       // fp16 attention out
__device__ __half g_wqkv16[LL*3*DD*DD];   // fp16 Wqkv TRANSPOSED [l][n][k]
__device__ __half g_wout16[LL*DD*DD];     // fp16 Wout TRANSPOSED [l][n][k]
__device__ int    g_mki[LL*BB*HH];        // per (l,b,h) max ||k||^2 (float bits)

#define ONESH2 0x3C003C00u                // half2(1.0, 1.0)

// -------- helpers --------
__device__ __forceinline__ void mma16h(float* d, const unsigned* a, unsigned b0, unsigned b1) {
    asm volatile(
        "mma.sync.aligned.m16n8k16.row.col.f32.f16.f16.f32 "
        "{%0,%1,%2,%3}, {%4,%5,%6,%7}, {%8,%9}, {%0,%1,%2,%3};\n"
        : "+f"(d[0]), "+f"(d[1]), "+f"(d[2]), "+f"(d[3])
        : "r"(a[0]), "r"(a[1]), "r"(a[2]), "r"(a[3]), "r"(b0), "r"(b1));
}
__device__ __forceinline__ void ldsm4(unsigned* r, unsigned saddr) {
    asm volatile("ldmatrix.sync.aligned.m8n8.x4.shared.b16 {%0,%1,%2,%3}, [%4];"
        : "=r"(r[0]), "=r"(r[1]), "=r"(r[2]), "=r"(r[3]) : "r"(saddr));
}
__device__ __forceinline__ void ldsm2(unsigned* r, unsigned saddr) {
    asm volatile("ldmatrix.sync.aligned.m8n8.x2.shared.b16 {%0,%1}, [%2];"
        : "=r"(r[0]), "=r"(r[1]) : "r"(saddr));
}
__device__ __forceinline__ unsigned pkh2(float lo, float hi) {
    __half2 h = __floats2half2_rn(lo, hi);
    return *reinterpret_cast<unsigned*>(&h);
}
__device__ __forceinline__ unsigned ex2h2(unsigned x) {
    unsigned r;
    asm("ex2.approx.f16x2 %0, %1;" : "=r"(r) : "r"(x));
    return r;
}
// packed fp32x2 helpers (HMMA C-frag pairs are consecutive aligned regs)
__device__ __forceinline__ unsigned long long pk64(float lo, float hi) {
    unsigned long long r;
    asm("mov.b64 %0, {%1,%2};" : "=l"(r) : "f"(lo), "f"(hi));
    return r;
}
__device__ __forceinline__ unsigned long long fma2(unsigned long long a,
                                                   unsigned long long b,
                                                   unsigned long long c) {
    unsigned long long r;
    asm("fma.rn.f32x2 %0, %1, %2, %3;" : "=l"(r) : "l"(a), "l"(b), "l"(c));
    return r;
}
__device__ __forceinline__ unsigned f32x2h2(unsigned long long p) {
    float lo, hi; unsigned r;
    asm("mov.b64 {%0,%1}, %2;" : "=f"(lo), "=f"(hi) : "l"(p));
    asm("cvt.rn.f16x2.f32 %0, %1, %2;" : "=r"(r) : "f"(hi), "f"(lo));
    return r;
}
__device__ __forceinline__ unsigned prmt(unsigned a, unsigned b, unsigned sel) {
    unsigned r;
    asm("prmt.b32 %0, %1, %2, %3;" : "=r"(r) : "r"(a), "r"(b), "r"(sel));
    return r;
}
__device__ __forceinline__ void cp16(void* smem, const void* g) {
    unsigned a = (unsigned)__cvta_generic_to_shared(smem);
    asm volatile("cp.async.cg.shared.global [%0], [%1], 16;\n" :: "r"(a), "l"(g));
}
__device__ __forceinline__ void cp_commit() { asm volatile("cp.async.commit_group;\n"); }
template<int N> __device__ __forceinline__ void cp_wait() {
    asm volatile("cp.async.wait_group %0;\n" :: "n"(N));
}

// ============================================================
// 0. Weight transpose + fp16 convert, both tensors in one launch.
// ============================================================
__global__ void transp_kernel(const float* __restrict__ Wqkv,
                              const float* __restrict__ Wout,
                              __half* __restrict__ dq,
                              __half* __restrict__ dw) {
    __shared__ float tile[32][33];
    int k0 = blockIdx.x * 32;
    int by = blockIdx.y;
    int l  = blockIdx.z;
    const float* s; __half* d; int N, n0;
    if (by < 24) { N = 3 * DD; n0 = by * 32;
                   s = Wqkv + (size_t)l * DD * N; d = dq + (size_t)l * DD * N; }
    else         { N = DD;     n0 = (by - 24) * 32;
                   s = Wout + (size_t)l * DD * N; d = dw + (size_t)l * DD * N; }
    for (int i = threadIdx.y; i < 32; i += 8)
        tile[i][threadIdx.x] = s[(size_t)(k0 + i) * N + n0 + threadIdx.x];
    __syncthreads();
    for (int i = threadIdx.y; i < 32; i += 8)
        d[(size_t)(n0 + i) * DD + k0 + threadIdx.x] = __float2half_rn(tile[threadIdx.x][i]);
}

// ============================================================
// 1. Projection: h = x @ Wp + bp + pos  (fp32 + fp16 copy)
// ============================================================
__global__ void proj_kernel(const float* __restrict__ x,
                            const float* __restrict__ Wp,
                            const float* __restrict__ bp,
                            const float* __restrict__ pos) {
    int idx = blockIdx.x * blockDim.x + threadIdx.x;
    if (idx < LL * BB * HH) g_mki[idx] = 0;
    if (idx >= NROW * DD) return;
    int row = idx / DD;
    int col = idx - row * DD;
    int t = row & (TT - 1);
    const float* xr = x + row * IN_DIM;
    float s = bp[col] + pos[t * DD + col];
#pragma unroll
    for (int i = 0; i < IN_DIM; i++)
        s = fmaf(xr[i], Wp[i * DD + col], s);
    g_h[idx] = s;
    g_h16[idx] = __float2half_rn(s);
}

// ============================================================
// 2. QKV GEMM (fp16 m16n8k16): g_qkvh = g_h16 @ W^T + bqkv
//    Block 128x128, 8 warps (2m x 4n), warp 64x32, 2 blocks/SM.
//    4-stage cp.async ring. Fragment loads via ldmatrix.x4
//    (stride-20 rows tile all 8 bank-groups: conflict-free).
// ============================================================
#define QST_A 2560      // words per A stage (128*20)
#define QST_B 2560      // words per B stage (128*20)
#define QSMEM_BYTES ((4*(QST_A+QST_B))*4)

extern __shared__ float dynsmem[];

__global__ __launch_bounds__(256, 2)
void qkv_gemm_kernel(int layer, const float* __restrict__ bias) {
    unsigned* As = (unsigned*)dynsmem;          // [4][128][20]
    unsigned* Bs = As + 4 * QST_A;              // [4][128][20]
    const __half* __restrict__ A = g_h16;
    const __half* __restrict__ Bmat = g_wqkv16 + (size_t)layer * 3 * DD * DD; // [n][k]
    const int N = 3 * DD;

    const int tid  = threadIdx.x;
    const int lane = tid & 31;
    const int g    = lane >> 2;
    const int q    = lane & 3;
    const int warp = tid >> 5;
    const int wm   = (warp & 1) * 64;
    const int wn   = (warp >> 1) * 32;
    const int bm   = blockIdx.y * 128;
    const int bn   = blockIdx.x * 128;

    const unsigned smem0 = (unsigned)__cvta_generic_to_shared(dynsmem);
    // ldmatrix provider patterns:
    // A x4: m0 rows base+il w kb | m1 rows base+8+il w kb | m2 rows base+il w kb+4 | m3 rows base+8+il w kb+4
    const int aRow = ((lane >> 3) & 1) * 8 + (lane & 7);
    const int aW   = (lane >> 4) * 4;
    // B x4: m0 rows base+il w kb | m1 rows base+il w kb+4 | m2 rows base+8+il w kb | m3 rows base+8+il w kb+4
    const int bRow = (lane >> 4) * 8 + (lane & 7);
    const int bW   = ((lane >> 3) & 1) * 4;

    auto issue = [&](int s) {
        int k0 = s * 32;
        unsigned* Asb = As + (s & 3) * QST_A;
        unsigned* Bsb = Bs + (s & 3) * QST_B;
#pragma unroll
        for (int p = 0; p < 2; p++) {
            int c = tid + p * 256;
            int r = c >> 2, cw = (c & 3) * 4;
            cp16(&Asb[r * 20 + cw], A + (size_t)(bm + r) * DD + k0 + cw * 2);
        }
#pragma unroll
        for (int p = 0; p < 2; p++) {
            int c = tid + p * 256;
            int r = c >> 2, cw = (c & 3) * 4;
            cp16(&Bsb[r * 20 + cw], Bmat + (size_t)(bn + r) * DD + k0 + cw * 2);
        }
    };

    float acc[4][4][4];
#pragma unroll
    for (int mc = 0; mc < 4; mc++)
#pragma unroll
        for (int nc = 0; nc < 4; nc++)
#pragma unroll
            for (int i = 0; i < 4; i++) acc[mc][nc][i] = 0.0f;

    issue(0); cp_commit();
    issue(1); cp_commit();
    issue(2); cp_commit();

    const int NS = DD / 32;   // 8
    for (int s = 0; s < NS; s++) {
        cp_wait<2>();
        __syncthreads();
        if (s + 3 < NS) issue(s + 3);
        cp_commit();

        const unsigned aBase = smem0 + ((s & 3) * QST_A) * 4;
        const unsigned bBase = smem0 + (4 * QST_A + (s & 3) * QST_B) * 4;
#pragma unroll
        for (int kc = 0; kc < 2; kc++) {
            int kb = kc * 8;
            unsigned af[4][4], bf[4][2];
#pragma unroll
            for (int mc = 0; mc < 4; mc++)
                ldsm4(af[mc], aBase + ((wm + mc * 16 + aRow) * 20 + kb + aW) * 4);
#pragma unroll
            for (int p = 0; p < 2; p++) {
                unsigned t[4];
                ldsm4(t, bBase + ((wn + p * 16 + bRow) * 20 + kb + bW) * 4);
                bf[2*p][0]   = t[0]; bf[2*p][1]   = t[1];
                bf[2*p+1][0] = t[2]; bf[2*p+1][1] = t[3];
            }
#pragma unroll
            for (int mc = 0; mc < 4; mc++)
#pragma unroll
                for (int nc = 0; nc < 4; nc++)
                    mma16h(acc[mc][nc], af[mc], bf[nc][0], bf[nc][1]);
        }
    }

    // epilogue: + bias, pack to fp16; K blocks also track max ||k||^2
    unsigned* qkw = reinterpret_cast<unsigned*>(g_qkvh);
    const bool isK = (bn == 256 || bn == 384);   // K cols [256,512)
    float mxss = 0.0f;
#pragma unroll
    for (int mc = 0; mc < 4; mc++) {
        float ssA = 0.0f, ssB = 0.0f;
#pragma unroll
        for (int nc = 0; nc < 4; nc++) {
            int row = bm + wm + mc * 16 + g;
            int col = bn + wn + nc * 8 + 2 * q;
            float2 bi = *(const float2*)&bias[col];
            float v0 = acc[mc][nc][0] + bi.x;
            float v1 = acc[mc][nc][1] + bi.y;
            float v2 = acc[mc][nc][2] + bi.x;
            float v3 = acc[mc][nc][3] + bi.y;
            qkw[(size_t)row * (N/2) + col/2]       = pkh2(v0, v1);
            qkw[(size_t)(row + 8) * (N/2) + col/2] = pkh2(v2, v3);
            ssA = fmaf(v0, v0, fmaf(v1, v1, ssA));
            ssB = fmaf(v2, v2, fmaf(v3, v3, ssB));
        }
        if (isK) {
            ssA += __shfl_xor_sync(0xffffffffu, ssA, 1);
            ssA += __shfl_xor_sync(0xffffffffu, ssA, 2);
            ssB += __shfl_xor_sync(0xffffffffu, ssB, 1);
            ssB += __shfl_xor_sync(0xffffffffu, ssB, 2);
            mxss = fmaxf(mxss, fmaxf(ssA, ssB));
        }
    }
    if (isK) {
        mxss = fmaxf(mxss, __shfl_xor_sync(0xffffffffu, mxss, 4));
        mxss = fmaxf(mxss, __shfl_xor_sync(0xffffffffu, mxss, 8));
        mxss = fmaxf(mxss, __shfl_xor_sync(0xffffffffu, mxss, 16));
        if (lane == 0) {
            int b = bm >> 10;                       // 1024 rows per batch
            int hd = (bn + wn - 256) >> 5;          // head of this warp
            atomicMax(&g_mki[layer * BB * HH + b * HH + hd], __float_as_int(mxss));
        }
    }
}

// ============================================================
// 3. Flash attention: fp16 MMA, Cauchy-Schwarz bounded softmax,
//    ex2.approx.f16x2, packed fma.rn.f32x2 exp args,
//    l via ones-immediate MMA. K fragments via ldmatrix.x2.
// ============================================================
__global__ __launch_bounds__(128, 4)
void attn_tc_kernel(int layer) {
    __shared__ unsigned Khs[2][32][20];   // [key][dim half2-word]
    __shared__ unsigned Vhs[2][16][40];   // [keypair][dim], stride 40

    const int tid  = threadIdx.x;
    const int lane = tid & 31;
    const int g    = lane >> 2;
    const int q    = lane & 3;
    const int warp = tid >> 5;
    const int h    = blockIdx.y;
    const int b    = blockIdx.z;
    const int qrow0 = blockIdx.x * 128 + warp * 32;

    const float qs = 0.17677669529663687f * 1.4426950408889634f; // scale*log2e
    const int RW = 3 * DD;
    const int RWW = RW / 2;

    const __half* kg = g_qkvh + (size_t)b * TT * RW + DD + h * DK;
    const __half* vg = g_qkvh + (size_t)b * TT * RW + 2 * DD + h * DK;
    const unsigned* qw = reinterpret_cast<const unsigned*>(
        g_qkvh + (size_t)(b * TT + qrow0) * RW + h * DK);

    const int kkey = tid >> 2;            // 0..31
    const int kwg  = (tid & 3) * 4;       // word offset 0,4,8,12
    const int vj  = tid >> 3;             // 0..15
    const int vdg = (tid & 7) * 4;        // dims vdg..vdg+3

    const unsigned kbase = (unsigned)__cvta_generic_to_shared(&Khs[0][0][0]);
    // ldmatrix.x2 providers (lanes 0-15): rows il, word half sel
    const int kRow = lane & 7;
    const int kW   = ((lane >> 3) & 1) * 4;

    // prologue tile 0
    cp16(&Khs[0][kkey][kwg], kg + (size_t)kkey * RW + kwg * 2);
    cp_commit();
    {
        uint2 wa = *(const uint2*)(vg + (size_t)(2 * vj) * RW + vdg);
        uint2 wb = *(const uint2*)(vg + (size_t)(2 * vj + 1) * RW + vdg);
        uint4 p;
        p.x = prmt(wa.x, wb.x, 0x5410); p.y = prmt(wa.x, wb.x, 0x7632);
        p.z = prmt(wa.y, wb.y, 0x5410); p.w = prmt(wa.y, wb.y, 0x7632);
        *(uint4*)&Vhs[0][vj][vdg] = p;
    }

    // Q A-fragments (fp16 words straight from memory)
    unsigned qa[2][2][4];
#pragma unroll
    for (int mc = 0; mc < 2; mc++)
#pragma unroll
        for (int kc = 0; kc < 2; kc++) {
            int r = mc * 16 + g;
            qa[mc][kc][0] = qw[(size_t)r * RWW + kc * 8 + q];
            qa[mc][kc][1] = qw[(size_t)(r + 8) * RWW + kc * 8 + q];
            qa[mc][kc][2] = qw[(size_t)r * RWW + kc * 8 + q + 4];
            qa[mc][kc][3] = qw[(size_t)(r + 8) * RWW + kc * 8 + q + 4];
        }

    // Per-row exp bias: eb = 11 - ||q||*M_k*qs (packed f32x2 duplicates)
    const float Mk = sqrtf(__int_as_float(g_mki[layer * BB * HH + b * HH + h]));
    const unsigned long long qs2 = pk64(qs, qs);
    unsigned long long eb2[2][2];
#pragma unroll
    for (int mc = 0; mc < 2; mc++) {
        float a0 = 0.0f, a1 = 0.0f;
#pragma unroll
        for (int kc = 0; kc < 2; kc++) {
            float2 f;
            f = __half22float2(*reinterpret_cast<__half2*>(&qa[mc][kc][0]));
            a0 = fmaf(f.x, f.x, fmaf(f.y, f.y, a0));
            f = __half22float2(*reinterpret_cast<__half2*>(&qa[mc][kc][2]));
            a0 = fmaf(f.x, f.x, fmaf(f.y, f.y, a0));
            f = __half22float2(*reinterpret_cast<__half2*>(&qa[mc][kc][1]));
            a1 = fmaf(f.x, f.x, fmaf(f.y, f.y, a1));
            f = __half22float2(*reinterpret_cast<__half2*>(&qa[mc][kc][3]));
            a1 = fmaf(f.x, f.x, fmaf(f.y, f.y, a1));
        }
        a0 += __shfl_xor_sync(0xffffffffu, a0, 1);
        a0 += __shfl_xor_sync(0xffffffffu, a0, 2);
        a1 += __shfl_xor_sync(0xffffffffu, a1, 1);
        a1 += __shfl_xor_sync(0xffffffffu, a1, 2);
        float e0 = 11.0f - sqrtf(a0) * Mk * qs;
        float e1 = 11.0f - sqrtf(a1) * Mk * qs;
        eb2[mc][0] = pk64(e0, e0);
        eb2[mc][1] = pk64(e1, e1);
    }

    float oacc[2][4][4];
    float lacc[2][4];
#pragma unroll
    for (int mc = 0; mc < 2; mc++) {
#pragma unroll
        for (int i = 0; i < 4; i++) lacc[mc][i] = 0.0f;
#pragma unroll
        for (int nc = 0; nc < 4; nc++)
#pragma unroll
            for (int i = 0; i < 4; i++) oacc[mc][nc][i] = 0.0f;
    }

    const int NT = TT / 32;
    for (int t = 0; t < NT; t++) {
        int buf = t & 1;
        int nb  = buf ^ 1;
        uint2 wa, wb;
        if (t + 1 < NT) {
            int k0 = (t + 1) * 32;
            cp16(&Khs[nb][kkey][kwg], kg + (size_t)(k0 + kkey) * RW + kwg * 2);
            cp_commit();
            wa = *(const uint2*)(vg + (size_t)(k0 + 2 * vj) * RW + vdg);
            wb = *(const uint2*)(vg + (size_t)(k0 + 2 * vj + 1) * RW + vdg);
            cp_wait<1>();
        } else {
            cp_wait<0>();
        }
        __syncthreads();

        // ---- S = Q K^T (fp16 k16), K frags via ldmatrix.x2 ----
        float sf[2][4][4];
#pragma unroll
        for (int mc = 0; mc < 2; mc++)
#pragma unroll
            for (int nc = 0; nc < 4; nc++)
#pragma unroll
                for (int i = 0; i < 4; i++) sf[mc][nc][i] = 0.0f;

        const unsigned kBuf = kbase + buf * (32 * 20 * 4);
#pragma unroll
        for (int nc = 0; nc < 4; nc++) {
#pragma unroll
            for (int kc = 0; kc < 2; kc++) {
                unsigned bk[2];
                ldsm2(bk, kBuf + ((nc * 8 + kRow) * 20 + kc * 8 + kW) * 4);
                mma16h(sf[0][nc], qa[0][kc], bk[0], bk[1]);
                mma16h(sf[1][nc], qa[1][kc], bk[0], bk[1]);
            }
        }

        // ---- fused softmax + PV + l: exp args via packed f32x2 FMA ----
#pragma unroll
        for (int kk = 0; kk < 2; kk++) {
            unsigned pa0[4], pa1[4];
#pragma unroll
            for (int j = 0; j < 2; j++) {
                int nc = 2 * kk + j;
                pa0[2*j]   = ex2h2(f32x2h2(fma2(pk64(sf[0][nc][0], sf[0][nc][1]), qs2, eb2[0][0])));
                pa0[2*j+1] = ex2h2(f32x2h2(fma2(pk64(sf[0][nc][2], sf[0][nc][3]), qs2, eb2[0][1])));
                pa1[2*j]   = ex2h2(f32x2h2(fma2(pk64(sf[1][nc][0], sf[1][nc][1]), qs2, eb2[1][0])));
                pa1[2*j+1] = ex2h2(f32x2h2(fma2(pk64(sf[1][nc][2], sf[1][nc][3]), qs2, eb2[1][1])));
            }
#pragma unroll
            for (int dn = 0; dn < 4; dn++) {
                unsigned b0 = Vhs[buf][8*kk + q][dn * 8 + g];
                unsigned b1 = Vhs[buf][8*kk + q + 4][dn * 8 + g];
                mma16h(oacc[0][dn], pa0, b0, b1);
                mma16h(oacc[1][dn], pa1, b0, b1);
            }
            mma16h(lacc[0], pa0, ONESH2, ONESH2);
            mma16h(lacc[1], pa1, ONESH2, ONESH2);
        }

        // commit prefetched V tile
        if (t + 1 < NT) {
            uint4 p;
            p.x = prmt(wa.x, wb.x, 0x5410); p.y = prmt(wa.x, wb.x, 0x7632);
            p.z = prmt(wa.y, wb.y, 0x5410); p.w = prmt(wa.y, wb.y, 0x7632);
            *(uint4*)&Vhs[nb][vj][vdg] = p;
        }
        __syncthreads();
    }

    // ---- normalize (l from ones-MMA: no shuffles), store fp16 ----
    unsigned* ow = reinterpret_cast<unsigned*>(g_attnh);
#pragma unroll
    for (int mc = 0; mc < 2; mc++) {
        float inv0 = 1.0f / lacc[mc][0];
        float inv1 = 1.0f / lacc[mc][2];
        int r0 = b * TT + qrow0 + mc * 16 + g;
#pragma unroll
        for (int dn = 0; dn < 4; dn++) {
            int col = h * DK + dn * 8 + 2 * q;
            ow[(size_t)r0 * (DD/2) + col/2] =
                pkh2(oacc[mc][dn][0] * inv0, oacc[mc][dn][1] * inv0);
            ow[(size_t)(r0 + 8) * (DD/2) + col/2] =
                pkh2(oacc[mc][dn][2] * inv1, oacc[mc][dn][3] * inv1);
        }
    }
}

// ============================================================
// 4. Wout GEMM (fp16) + bias + residual + LayerNorm, fused.
//    Block 32x256, 8 warps of 32x32. ldmatrix fragment loads.
// ============================================================
#define WST_A 640       // words per A stage (32*20)
#define WST_B 5120      // words per B stage (256*20)
#define WRED_OFF (4*(WST_A+WST_B))
#define WSMEM_BYTES ((WRED_OFF+512)*4)

__global__ __launch_bounds__(256, 2)
void wout_ln_kernel(int layer, const float* __restrict__ bias,
                    const float* __restrict__ gamma,
                    const float* __restrict__ beta) {
    unsigned* As = (unsigned*)dynsmem;
    unsigned* Bs = As + 4 * WST_A;
    float* redS = dynsmem + WRED_OFF;       // [32][8]
    float* redQ = redS + 256;               // [32][8]
    const __half* __restrict__ A = g_attnh;
    const __half* __restrict__ Bmat = g_wout16 + (size_t)layer * DD * DD; // [n][k]

    const int tid  = threadIdx.x;
    const int lane = tid & 31;
    const int g    = lane >> 2;
    const int q    = lane & 3;
    const int warp = tid >> 5;
    const int wn   = warp * 32;
    const int bm   = blockIdx.x * 32;

    const unsigned smem0 = (unsigned)__cvta_generic_to_shared(dynsmem);
    const int aRow = ((lane >> 3) & 1) * 8 + (lane & 7);
    const int aW   = (lane >> 4) * 4;
    const int bRow = (lane >> 4) * 8 + (lane & 7);
    const int bW   = ((lane >> 3) & 1) * 4;

    auto issue = [&](int s) {
        int k0 = s * 32;
        unsigned* Asb = As + (s & 3) * WST_A;
        unsigned* Bsb = Bs + (s & 3) * WST_B;
        if (tid < 128) {
            int r = tid >> 2, cw = (tid & 3) * 4;
            cp16(&Asb[r * 20 + cw], A + (size_t)(bm + r) * DD + k0 + cw * 2);
        }
#pragma unroll
        for (int p = 0; p < 4; p++) {
            int c = tid + p * 256;
            int r = c >> 2, cw = (c & 3) * 4;
            cp16(&Bsb[r * 20 + cw], Bmat + (size_t)r * DD + k0 + cw * 2);
        }
    };

    float acc[2][4][4];
#pragma unroll
    for (int mc = 0; mc < 2; mc++)
#pragma unroll
        for (int nc = 0; nc < 4; nc++)
#pragma unroll
            for (int i = 0; i < 4; i++) acc[mc][nc][i] = 0.0f;

    issue(0); cp_commit();
    issue(1); cp_commit();
    issue(2); cp_commit();

    const int NS = DD / 32;    // 8
    for (int s = 0; s < NS; s++) {
        cp_wait<2>();
        __syncthreads();
        if (s + 3 < NS) issue(s + 3);
        cp_commit();

        const unsigned aBase = smem0 + ((s & 3) * WST_A) * 4;
        const unsigned bBase = smem0 + (4 * WST_A + (s & 3) * WST_B) * 4;
#pragma unroll
        for (int kc = 0; kc < 2; kc++) {
            int kb = kc * 8;
            unsigned af[2][4], bf[4][2];
#pragma unroll
            for (int mc = 0; mc < 2; mc++)
                ldsm4(af[mc], aBase + ((mc * 16 + aRow) * 20 + kb + aW) * 4);
#pragma unroll
            for (int p = 0; p < 2; p++) {
                unsigned t[4];
                ldsm4(t, bBase + ((wn + p * 16 + bRow) * 20 + kb + bW) * 4);
                bf[2*p][0]   = t[0]; bf[2*p][1]   = t[1];
                bf[2*p+1][0] = t[2]; bf[2*p+1][1] = t[3];
            }
#pragma unroll
            for (int mc = 0; mc < 2; mc++)
#pragma unroll
                for (int nc = 0; nc < 4; nc++)
                    mma16h(acc[mc][nc], af[mc], bf[nc][0], bf[nc][1]);
        }
    }
    __syncthreads();

    // epilogue part 1: + bias + residual (fp32), partial row stats
#pragma unroll
    for (int mc = 0; mc < 2; mc++) {
        int rlo = bm + mc * 16 + g;
        float ssA = 0.f, sqA = 0.f, ssB = 0.f, sqB = 0.f;
#pragma unroll
        for (int nc = 0; nc < 4; nc++) {
            int col = wn + nc * 8 + 2 * q;
            float2 bi = *(const float2*)&bias[col];
            float2 h0 = *(const float2*)&g_h[(size_t)rlo * DD + col];
            float2 h1 = *(const float2*)&g_h[(size_t)(rlo + 8) * DD + col];
            acc[mc][nc][0] += bi.x + h0.x;
            acc[mc][nc][1] += bi.y + h0.y;
            acc[mc][nc][2] += bi.x + h1.x;
            acc[mc][nc][3] += bi.y + h1.y;
            ssA += acc[mc][nc][0] + acc[mc][nc][1];
            sqA += acc[mc][nc][0]*acc[mc][nc][0] + acc[mc][nc][1]*acc[mc][nc][1];
            ssB += acc[mc][nc][2] + acc[mc][nc][3];
            sqB += acc[mc][nc][2]*acc[mc][nc][2] + acc[mc][nc][3]*acc[mc][nc][3];
        }
        ssA += __shfl_xor_sync(0xffffffffu, ssA, 1); ssA += __shfl_xor_sync(0xffffffffu, ssA, 2);
        sqA += __shfl_xor_sync(0xffffffffu, sqA, 1); sqA += __shfl_xor_sync(0xffffffffu, sqA, 2);
        ssB += __shfl_xor_sync(0xffffffffu, ssB, 1); ssB += __shfl_xor_sync(0xffffffffu, ssB, 2);
        sqB += __shfl_xor_sync(0xffffffffu, sqB, 1); sqB += __shfl_xor_sync(0xffffffffu, sqB, 2);
        if (q == 0) {
            int rl = mc * 16 + g;
            redS[rl * 8 + warp] = ssA;  redQ[rl * 8 + warp] = sqA;
            redS[(rl + 8) * 8 + warp] = ssB;  redQ[(rl + 8) * 8 + warp] = sqB;
        }
    }
    __syncthreads();

    // epilogue part 2: normalize + store (fp32 + fp16)
    unsigned* hw = reinterpret_cast<unsigned*>(g_h16);
#pragma unroll
    for (int mc = 0; mc < 2; mc++) {
        int rlA = mc * 16 + g;
        int rlB = rlA + 8;
        float sA = 0.f, qA = 0.f, sB = 0.f, qB = 0.f;
#pragma unroll
        for (int w = 0; w < 8; w++) {
            sA += redS[rlA * 8 + w];  qA += redQ[rlA * 8 + w];
            sB += redS[rlB * 8 + w];  qB += redQ[rlB * 8 + w];
        }
        float muA = sA * (1.0f / DD);
        float muB = sB * (1.0f / DD);
        float rsA = rsqrtf(qA * (1.0f / DD) - muA * muA + LN_EPS);
        float rsB = rsqrtf(qB * (1.0f / DD) - muB * muB + LN_EPS);
        int rowA = bm + rlA;
#pragma unroll
        for (int nc = 0; nc < 4; nc++) {
            int col = wn + nc * 8 + 2 * q;
            float2 ga = *(const float2*)&gamma[col];
            float2 be = *(const float2*)&beta[col];
            float v0 = (acc[mc][nc][0] - muA) * rsA * ga.x + be.x;
            float v1 = (acc[mc][nc][1] - muA) * rsA * ga.y + be.y;
            float v2 = (acc[mc][nc][2] - muB) * rsB * ga.x + be.x;
            float v3 = (acc[mc][nc][3] - muB) * rsB * ga.y + be.y;
            *(float2*)&g_h[(size_t)rowA * DD + col]       = make_float2(v0, v1);
            *(float2*)&g_h[(size_t)(rowA + 8) * DD + col] = make_float2(v2, v3);
            hw[(size_t)rowA * (DD/2) + col/2]       = pkh2(v0, v1);
            hw[(size_t)(rowA + 8) * (DD/2) + col/2] = pkh2(v2, v3);
        }
    }
}

// ============================================================
// 5. Head
// ============================================================
__global__ void head_kernel(const float* __restrict__ Wo,
                            const float* __restrict__ bo,
                            float* __restrict__ out) {
    int b = blockIdx.x / 3;
    int j = blockIdx.x - b * 3;
    int lane = threadIdx.x;
    const float* hr = g_h + (size_t)(b * TT + (TT - 1)) * DD;
    float s = 0.0f;
    for (int d = lane; d < DD; d += 32)
        s = fmaf(hr[d], Wo[d * 3 + j], s);
#pragma unroll
    for (int o = 16; o > 0; o >>= 1)
        s += __shfl_xor_sync(0xffffffffu, s, o);
    if (lane == 0) out[b * 3 + j] = s + bo[j];
}

// ============================================================
// launch
// ============================================================
extern "C" void kernel_launch(void* const* d_in, const int* in_sizes, int n_in,
                              void* d_out, int out_size) {
    const float* x    = (const float*)d_in[0];
    const float* Wp   = (const float*)d_in[1];
    const float* bp   = (const float*)d_in[2];
    const float* pos  = (const float*)d_in[3];
    const float* Wqkv = (const float*)d_in[4];
    const float* bqkv = (const float*)d_in[5];
    const float* Wout = (const float*)d_in[6];
    const float* bout = (const float*)d_in[7];
    const float* ln_g = (const float*)d_in[8];
    const float* ln_b = (const float*)d_in[9];
    const float* Wo   = (const float*)d_in[10];
    const float* bo   = (const float*)d_in[11];
    float* out = (float*)d_out;

    cudaFuncSetAttribute(qkv_gemm_kernel, cudaFuncAttributeMaxDynamicSharedMemorySize, QSMEM_BYTES);
    cudaFuncSetAttribute(wout_ln_kernel,  cudaFuncAttributeMaxDynamicSharedMemorySize, WSMEM_BYTES);

    __half* d_wqkv16 = nullptr;
    __half* d_wout16 = nullptr;
    cudaGetSymbolAddress((void**)&d_wqkv16, g_wqkv16);
    cudaGetSymbolAddress((void**)&d_wout16, g_wout16);

    transp_kernel<<<dim3(DD/32, 32, LL), dim3(32, 8)>>>(Wqkv, Wout, d_wqkv16, d_wout16);
    proj_kernel<<<(NROW * DD + 255) / 256, 256>>>(x, Wp, bp, pos);

    for (int l = 0; l < LL; l++) {
        qkv_gemm_kernel<<<dim3((3 * DD) / 128, NROW / 128), 256, QSMEM_BYTES>>>(
            l, bqkv + (size_t)l * 3 * DD);
        attn_tc_kernel<<<dim3(TT / 128, HH, BB), 128>>>(l);
        wout_ln_kernel<<<NROW / 32, 256, WSMEM_BYTES>>>(
            l, bout + (size_t)l * DD, ln_g + (size_t)l * DD, ln_b + (size_t)l * DD);
    }

    head_kernel<<<24, 32>>>(Wo, bo, out);
}